// round 3
// baseline (speedup 1.0000x reference)
#include <cuda_runtime.h>
#include <math.h>
#include <stdint.h>

// Problem constants (shapes fixed by the dataset)
#define NNODES 50000
#define NEDGES 800000
#define EETOT  (NNODES + NEDGES)
#define C64    64

// ---------------- scratch (static device globals; no allocation allowed) ---
__device__ __align__(256) float g_xl [NNODES * C64];
__device__ __align__(256) float g_xr [NNODES * C64];
__device__ __align__(256) float g_agg[NNODES * C64];
__device__ __align__(256) float g_h  [NNODES * C64];
__device__ __align__(256) float g_e  [EETOT];
__device__ __align__(256) unsigned g_m[NNODES];
__device__ __align__(256) float g_s [NNODES];
__device__ __align__(256) float g_st[128];          // per-channel sum / sumsq
__device__ int g_idx64;                              // 1 if edge_index is int64

// ---------------- helpers ---------------------------------------------------
__device__ __forceinline__ unsigned fenc(float f) {
    unsigned u = __float_as_uint(f);
    return u ^ ((u >> 31) ? 0xFFFFFFFFu : 0x80000000u);
}
__device__ __forceinline__ float fdec(unsigned u) {
    return __uint_as_float(u ^ ((u >> 31) ? 0x80000000u : 0xFFFFFFFFu));
}
__device__ __forceinline__ int load_idx(const void* ei, long long pos) {
    if (g_idx64) return (int)((const long long*)ei)[pos];
    return ((const int*)ei)[pos];
}

// Detect int64 vs int32 edge_index: for nonnegative int64 values, every odd
// 32-bit word (high half) is 0. For int32 data, odd words are node ids
// (P[all 64 sampled == 0] ~ (1/50000)^64 ~ 0).
__global__ void detect_k(const int* ei32, int E) {
    int t = threadIdx.x;  // 32 threads
    int nz = 0;
    if (2 * t + 1 < 2 * E)        nz |= (ei32[2 * t + 1] != 0);
    if (2 * (t + 32) + 1 < 2 * E) nz |= (ei32[2 * (t + 32) + 1] != 0);
    nz = __any_sync(0xffffffffu, nz);
    if (t == 0) g_idx64 = nz ? 0 : 1;
}

__global__ void init_k(float* agg, unsigned* m, float* s, float* st,
                       int nAgg, int nNodes) {
    int i = blockIdx.x * blockDim.x + threadIdx.x;
    if (i < nAgg) agg[i] = 0.f;
    if (i < nNodes) { m[i] = 0x007FFFFFu /* fenc(-inf) */; s[i] = 0.f; }
    if (i < 128) st[i] = 0.f;
}

// ---------------- dual GEMM: O0 = A @ W0, O1 = A @ W1 ----------------------
// A: M x K (K in {64,128}), W0/W1: K x 64 row-major, O0/O1: M x 64.
// Block computes a 64-row x 128-col tile; 256 threads, 8x4 register tile.
__global__ void gemm_dual(const float* __restrict__ A,
                          const float* __restrict__ W0,
                          const float* __restrict__ W1,
                          float* __restrict__ O0, float* __restrict__ O1,
                          int M, int K) {
    __shared__ float xs[64][64];    // 16 KB
    __shared__ float ws[64][128];   // 32 KB  (total 48 KB)
    const int t = threadIdx.x;
    const int row0 = blockIdx.x * 64;
    const int cg = t & 31;          // column group (4 cols)
    const int rg = t >> 5;          // row group (8 rows)
    const int colbase = cg * 4;
    const int rowbase = rg * 8;

    float acc[8][4];
#pragma unroll
    for (int i = 0; i < 8; ++i)
#pragma unroll
        for (int j = 0; j < 4; ++j) acc[i][j] = 0.f;

    for (int k0 = 0; k0 < K; k0 += 64) {
        // stage A tile (64 rows x 64 k)
        for (int l = t; l < 64 * 64; l += 256) {
            int r = l >> 6, k = l & 63;
            int grow = row0 + r;
            xs[r][k] = (grow < M) ? A[(size_t)grow * K + k0 + k] : 0.f;
        }
        // stage W tile (64 k x [W0|W1])
        for (int l = t; l < 64 * 128; l += 256) {
            int k = l >> 7, c = l & 127;
            ws[k][c] = (c < 64) ? W0[(size_t)(k0 + k) * 64 + c]
                                : W1[(size_t)(k0 + k) * 64 + (c - 64)];
        }
        __syncthreads();
#pragma unroll 8
        for (int k = 0; k < 64; ++k) {
            float4 b = *(const float4*)&ws[k][colbase];
#pragma unroll
            for (int i = 0; i < 8; ++i) {
                float a = xs[rowbase + i][k];   // warp broadcast
                acc[i][0] += a * b.x; acc[i][1] += a * b.y;
                acc[i][2] += a * b.z; acc[i][3] += a * b.w;
            }
        }
        __syncthreads();
    }

    float* O = (colbase < 64) ? O0 : O1;
    const int cb = colbase & 63;
#pragma unroll
    for (int i = 0; i < 8; ++i) {
        int grow = row0 + rowbase + i;
        if (grow < M)
            *(float4*)&O[(size_t)grow * 64 + cb] =
                make_float4(acc[i][0], acc[i][1], acc[i][2], acc[i][3]);
    }
}

// ---------------- edge pass A: scores + segment max -------------------------
// One warp per edge. e = att . leakyrelu(xl[src] + xr[dst]); atomicMax m[dst].
__global__ void edge_scores(const void* __restrict__ ei,
                            const float* __restrict__ xl,
                            const float* __restrict__ xr,
                            const float* __restrict__ att,
                            float* __restrict__ e_out, unsigned* __restrict__ m,
                            int E, int EE) {
    int g = blockIdx.x * blockDim.x + threadIdx.x;
    int w = g >> 5, lane = g & 31;
    if (w >= EE) return;
    int src, dst;
    if (w < E) { src = load_idx(ei, w); dst = load_idx(ei, (long long)E + w); }
    else       { src = dst = w - E; }

    float2 a = ((const float2*)(xl + (size_t)src * 64))[lane];
    float2 b = ((const float2*)(xr + (size_t)dst * 64))[lane];
    float2 av = ((const float2*)att)[lane];
    float v0 = a.x + b.x, v1 = a.y + b.y;
    v0 = v0 > 0.f ? v0 : 0.2f * v0;
    v1 = v1 > 0.f ? v1 : 0.2f * v1;
    float e = v0 * av.x + v1 * av.y;
#pragma unroll
    for (int o = 16; o; o >>= 1) e += __shfl_xor_sync(0xffffffffu, e, o);
    if (lane == 0) {
        e_out[w] = e;
        atomicMax(&m[dst], fenc(e));
    }
}

// ---------------- edge pass B: p = exp(e - m[dst]); segment sum -------------
__global__ void edge_soft(const void* __restrict__ ei,
                          float* __restrict__ e_buf,
                          const unsigned* __restrict__ m, float* __restrict__ s,
                          int E, int EE) {
    int j = blockIdx.x * blockDim.x + threadIdx.x;
    if (j >= EE) return;
    int dst = (j < E) ? load_idx(ei, (long long)E + j) : j - E;
    float p = expf(e_buf[j] - fdec(m[dst]));
    e_buf[j] = p;
    atomicAdd(&s[dst], p);
}

// ---------------- edge pass C: agg[dst] += alpha * xl[src] ------------------
__global__ void edge_agg(const void* __restrict__ ei,
                         const float* __restrict__ p_buf,
                         const float* __restrict__ s,
                         const float* __restrict__ xl, float* __restrict__ agg,
                         int E, int EE) {
    int g = blockIdx.x * blockDim.x + threadIdx.x;
    int w = g >> 5, lane = g & 31;
    if (w >= EE) return;
    int src, dst;
    if (w < E) { src = load_idx(ei, w); dst = load_idx(ei, (long long)E + w); }
    else       { src = dst = w - E; }

    float alpha = p_buf[w] / (s[dst] + 1e-16f);
    float2 a = ((const float2*)(xl + (size_t)src * 64))[lane];
    float* dp = agg + (size_t)dst * 64 + 2 * lane;
    atomicAdd(dp,     alpha * a.x);
    atomicAdd(dp + 1, alpha * a.y);
}

// ---------------- per-channel sum & sumsq of (v + bias) ---------------------
__global__ void stats64(const float* __restrict__ v,
                        const float* __restrict__ bias,
                        float* __restrict__ st, int N) {
    int t = threadIdx.x;            // 256
    int c = t & 63;
    int r = blockIdx.x * 4 + (t >> 6);
    int stride = gridDim.x * 4;
    float b = bias[c];
    float s = 0.f, q = 0.f;
    for (; r < N; r += stride) {
        float x = v[(size_t)r * 64 + c] + b;
        s += x; q += x * x;
    }
    __shared__ float sh[256], sh2[256];
    sh[t] = s; sh2[t] = q;
    __syncthreads();
    if (t < 64) {
        s = sh[t] + sh[t + 64] + sh[t + 128] + sh[t + 192];
        q = sh2[t] + sh2[t + 64] + sh2[t + 128] + sh2[t + 192];
        atomicAdd(&st[c], s);
        atomicAdd(&st[64 + c], q);
    }
}

// ---------------- BatchNorm (affine) + ReLU ---------------------------------
__global__ void bn_relu(const float* __restrict__ v,
                        const float* __restrict__ bias,
                        const float* __restrict__ st,
                        const float* __restrict__ gamma,
                        const float* __restrict__ beta,
                        float* __restrict__ h, int N) {
    int i = blockIdx.x * blockDim.x + threadIdx.x;
    if (i >= N * 64) return;
    int c = i & 63;
    float invN = 1.f / (float)N;
    float mu = st[c] * invN;
    float var = st[64 + c] * invN - mu * mu;
    float x = (v[i] + bias[c] - mu) * rsqrtf(var + 1e-5f);
    x = x * gamma[c] + beta[c];
    h[i] = fmaxf(x, 0.f);
}

// ---------------- final head: BN(no affine) on [:,:32], softplus [:,32:] ----
__global__ void final_k(const float* __restrict__ v,
                        const float* __restrict__ bias,
                        const float* __restrict__ st,
                        float* __restrict__ out, int N) {
    int i = blockIdx.x * blockDim.x + threadIdx.x;
    if (i >= N * 64) return;
    int n = i >> 6, c = i & 63;
    float x = v[i] + bias[c];
    if (c < 32) {
        float invN = 1.f / (float)N;
        float mu = st[c] * invN;
        float var = st[64 + c] * invN - mu * mu;
        out[(size_t)n * 32 + c] = (x - mu) * rsqrtf(var + 1e-5f);
    } else {
        // numerically stable softplus: max(x,0) + log1p(exp(-|x|))
        float sp = fmaxf(x, 0.f) + log1pf(expf(-fabsf(x)));
        out[(size_t)N * 32 + (size_t)n * 32 + (c - 32)] = sp;
    }
}

// ---------------- host launcher ---------------------------------------------
extern "C" void kernel_launch(void* const* d_in, const int* in_sizes, int n_in,
                              void* d_out, int out_size) {
    const float* x    = (const float*)d_in[0];
    const void*  ei   = d_in[1];
    const float* Wl1  = (const float*)d_in[2];
    const float* Wr1  = (const float*)d_in[3];
    const float* att1 = (const float*)d_in[4];
    const float* b1   = (const float*)d_in[5];
    const float* ga1  = (const float*)d_in[6];
    const float* be1  = (const float*)d_in[7];
    const float* Wl2  = (const float*)d_in[8];
    const float* Wr2  = (const float*)d_in[9];
    const float* att2 = (const float*)d_in[10];
    const float* b2   = (const float*)d_in[11];
    float* out = (float*)d_out;

    const int N  = in_sizes[0] / 128;   // 50000
    const int E  = in_sizes[1] / 2;     // 800000
    const int EE = E + N;               // + self loops
    const int nAgg = N * 64;

    float *p_xl, *p_xr, *p_agg, *p_h, *p_e, *p_s, *p_st;
    unsigned* p_m;
    cudaGetSymbolAddress((void**)&p_xl,  g_xl);
    cudaGetSymbolAddress((void**)&p_xr,  g_xr);
    cudaGetSymbolAddress((void**)&p_agg, g_agg);
    cudaGetSymbolAddress((void**)&p_h,   g_h);
    cudaGetSymbolAddress((void**)&p_e,   g_e);
    cudaGetSymbolAddress((void**)&p_m,   g_m);
    cudaGetSymbolAddress((void**)&p_s,   g_s);
    cudaGetSymbolAddress((void**)&p_st,  g_st);

    const int TB = 256;
    const int gInit  = (nAgg + TB - 1) / TB;
    const int gEdgeW = ((EE * 32) + TB - 1) / TB;   // warp per edge
    const int gEdgeT = (EE + TB - 1) / TB;          // thread per edge
    const int gGemm  = (N + 63) / 64;
    const int gElem  = (nAgg + TB - 1) / TB;

    detect_k<<<1, 32>>>((const int*)ei, E);

    // ---- layer 1 ----
    init_k<<<gInit, TB>>>(p_agg, p_m, p_s, p_st, nAgg, N);
    gemm_dual<<<gGemm, TB>>>(x, Wl1, Wr1, p_xl, p_xr, N, 128);
    edge_scores<<<gEdgeW, TB>>>(ei, p_xl, p_xr, att1, p_e, p_m, E, EE);
    edge_soft<<<gEdgeT, TB>>>(ei, p_e, p_m, p_s, E, EE);
    edge_agg<<<gEdgeW, TB>>>(ei, p_e, p_s, p_xl, p_agg, E, EE);
    stats64<<<256, TB>>>(p_agg, b1, p_st, N);
    bn_relu<<<gElem, TB>>>(p_agg, b1, p_st, ga1, be1, p_h, N);

    // ---- layer 2 ----
    init_k<<<gInit, TB>>>(p_agg, p_m, p_s, p_st, nAgg, N);
    gemm_dual<<<gGemm, TB>>>(p_h, Wl2, Wr2, p_xl, p_xr, N, 64);
    edge_scores<<<gEdgeW, TB>>>(ei, p_xl, p_xr, att2, p_e, p_m, E, EE);
    edge_soft<<<gEdgeT, TB>>>(ei, p_e, p_m, p_s, E, EE);
    edge_agg<<<gEdgeW, TB>>>(ei, p_e, p_s, p_xl, p_agg, E, EE);
    stats64<<<256, TB>>>(p_agg, b2, p_st, N);
    final_k<<<gElem, TB>>>(p_agg, b2, p_st, out, N);
}

// round 4
// speedup vs baseline: 1.6391x; 1.6391x over previous
#include <cuda_runtime.h>
#include <math.h>
#include <stdint.h>

// Problem constants (shapes fixed by the dataset)
#define NNODES 50000
#define NEDGES 800000
#define EETOT  (NNODES + NEDGES)
#define C64    64

// ---------------- scratch (static device globals; no allocation allowed) ---
__device__ __align__(256) float g_xl [NNODES * C64];
__device__ __align__(256) float g_xr [NNODES * C64];
__device__ __align__(256) float g_agg[NNODES * C64];
__device__ __align__(256) float g_h  [NNODES * C64];
__device__ __align__(256) int   g_srcb[EETOT];      // CSR src ids (sorted by dst)
__device__ __align__(256) int   g_off [NNODES];     // CSR row offsets
__device__ __align__(256) int   g_deg [NNODES];     // in-degree per node
__device__ __align__(256) int   g_cur [NNODES];     // scatter cursors
__device__ __align__(256) float g_st[128];          // per-channel sum / sumsq
__device__ int g_idx64;                              // 1 if edge_index is int64

// ---------------- helpers ---------------------------------------------------
__device__ __forceinline__ int load_idx(const void* ei, long long pos) {
    if (g_idx64) return (int)((const long long*)ei)[pos];
    return ((const int*)ei)[pos];
}

// Detect int64 vs int32 edge_index: for nonnegative int64 values, every odd
// 32-bit word (high half) is 0. For int32 data, odd words are node ids.
__global__ void detect_k(const int* ei32, int E) {
    int t = threadIdx.x;  // 32 threads
    int nz = 0;
    if (2 * t + 1 < 2 * E)        nz |= (ei32[2 * t + 1] != 0);
    if (2 * (t + 32) + 1 < 2 * E) nz |= (ei32[2 * (t + 32) + 1] != 0);
    nz = __any_sync(0xffffffffu, nz);
    if (t == 0) g_idx64 = nz ? 0 : 1;
}

// ---------------- CSR build: histogram, scan, scatter ------------------------
__global__ void hist_k(const void* __restrict__ ei, int* __restrict__ deg,
                       int E, int EE) {
    int i = blockIdx.x * blockDim.x + threadIdx.x;
    if (i >= EE) return;
    int dst = (i < E) ? load_idx(ei, (long long)E + i) : i - E;
    atomicAdd(&deg[dst], 1);
}

__global__ void scan_k(const int* __restrict__ deg, int* __restrict__ off,
                       int* __restrict__ cur, int N) {
    __shared__ int part[1024];
    int t = threadIdx.x;                 // 1024 threads, 1 block
    int chunk = (N + 1023) >> 10;
    int lo = t * chunk;
    int hi = lo + chunk; if (hi > N) hi = N;
    int s = 0;
    for (int i = lo; i < hi; ++i) s += deg[i];
    part[t] = s;
    __syncthreads();
    for (int d = 1; d < 1024; d <<= 1) {
        int u = (t >= d) ? part[t - d] : 0;
        __syncthreads();
        part[t] += u;
        __syncthreads();
    }
    int run = part[t] - s;               // exclusive prefix of this chunk
    for (int i = lo; i < hi; ++i) {
        off[i] = run; cur[i] = run;
        run += deg[i];
    }
}

__global__ void scatter_k(const void* __restrict__ ei, int* __restrict__ cur,
                          int* __restrict__ srcb, int E, int EE) {
    int i = blockIdx.x * blockDim.x + threadIdx.x;
    if (i >= EE) return;
    int src, dst;
    if (i < E) { src = load_idx(ei, i); dst = load_idx(ei, (long long)E + i); }
    else       { src = dst = i - E; }
    int pos = atomicAdd(&cur[dst], 1);
    srcb[pos] = src;
}

// ---------------- dual GEMM: O0 = A @ W0, O1 = A @ W1 ----------------------
// A: M x K (K in {64,128}), W0/W1: K x 64 row-major, O0/O1: M x 64.
// 128x128 tile, Kc=32, 256 threads, 8x8 register micro-tile.
__global__ void gemm_dual(const float* __restrict__ A,
                          const float* __restrict__ W0,
                          const float* __restrict__ W1,
                          float* __restrict__ O0, float* __restrict__ O1,
                          int M, int K) {
    __shared__ float As[128][36];   // [row][k] + pad  (18 KB)
    __shared__ float Ws[32][128];   // [k][col]        (16 KB)
    const int t  = threadIdx.x;
    const int tx = t & 15;          // 16 col groups of 8
    const int ty = t >> 4;          // 16 row groups of 8
    const int row0 = blockIdx.x * 128;

    float acc[8][8];
#pragma unroll
    for (int i = 0; i < 8; ++i)
#pragma unroll
        for (int j = 0; j < 8; ++j) acc[i][j] = 0.f;

    for (int k0 = 0; k0 < K; k0 += 32) {
        // stage A tile: 128 rows x 32 k, float4 per thread x4
#pragma unroll
        for (int l = t; l < 1024; l += 256) {
            int r = l >> 3, kq = l & 7;
            float4 v = make_float4(0.f, 0.f, 0.f, 0.f);
            if (row0 + r < M)
                v = *(const float4*)&A[(size_t)(row0 + r) * K + k0 + kq * 4];
            *(float4*)&As[r][kq * 4] = v;
        }
        // stage W tile: 32 k x [W0 | W1]
#pragma unroll
        for (int l = t; l < 1024; l += 256) {
            int kk = l >> 5, cq = l & 31;
            int c = cq * 4;
            const float* Wsrc = (c < 64)
                ? &W0[(size_t)(k0 + kk) * 64 + c]
                : &W1[(size_t)(k0 + kk) * 64 + (c - 64)];
            *(float4*)&Ws[kk][c] = *(const float4*)Wsrc;
        }
        __syncthreads();
#pragma unroll
        for (int k = 0; k < 32; ++k) {
            float a[8], b[8];
            *(float4*)&b[0] = *(const float4*)&Ws[k][tx * 8];
            *(float4*)&b[4] = *(const float4*)&Ws[k][tx * 8 + 4];
#pragma unroll
            for (int i = 0; i < 8; ++i) a[i] = As[ty * 8 + i][k];
#pragma unroll
            for (int i = 0; i < 8; ++i)
#pragma unroll
                for (int j = 0; j < 8; ++j) acc[i][j] += a[i] * b[j];
        }
        __syncthreads();
    }

    const int cb = tx * 8;
    float* O = (cb < 64) ? O0 : O1;
    const int cc = cb & 63;
#pragma unroll
    for (int i = 0; i < 8; ++i) {
        int r = row0 + ty * 8 + i;
        if (r < M) {
            *(float4*)&O[(size_t)r * 64 + cc] =
                make_float4(acc[i][0], acc[i][1], acc[i][2], acc[i][3]);
            *(float4*)&O[(size_t)r * 64 + cc + 4] =
                make_float4(acc[i][4], acc[i][5], acc[i][6], acc[i][7]);
        }
    }
}

// ---------------- fused GATv2 edge pass (node-parallel, online softmax) -----
// 8 lanes per dst node, each lane owns 8 channels (2 float4).
// Per incoming edge: e = att . leakyrelu(xl[src] + xr[dst]) via 3-stage
// butterfly; online softmax keeps running (m, s, acc) with rescale.
// No atomics, no per-edge buffers, xl[src] gathered exactly once.
__global__ void gat_fused(const int* __restrict__ srcb,
                          const int* __restrict__ off,
                          const int* __restrict__ deg,
                          const float* __restrict__ xl,
                          const float* __restrict__ xr,
                          const float* __restrict__ att,
                          float* __restrict__ agg, int N) {
    int g = blockIdx.x * blockDim.x + threadIdx.x;
    int node = g >> 3;
    int lane = g & 7;
    if (node >= N) return;

    const float4* xr4 = (const float4*)(xr + (size_t)node * 64) + lane * 2;
    float4 r0 = xr4[0], r1 = xr4[1];
    const float4* at4 = (const float4*)att + lane * 2;
    float4 a0 = at4[0], a1 = at4[1];

    int base = off[node];
    int cnt  = deg[node];

    float m = -1e30f, s = 0.f;
    float4 c0 = make_float4(0.f, 0.f, 0.f, 0.f);
    float4 c1 = make_float4(0.f, 0.f, 0.f, 0.f);

    for (int j = 0; j < cnt; ++j) {
        int src = __ldg(&srcb[base + j]);
        const float4* xl4 = (const float4*)(xl + (size_t)src * 64) + lane * 2;
        float4 l0 = xl4[0], l1 = xl4[1];

        float e, v;
        v = l0.x + r0.x; e  = a0.x * (v > 0.f ? v : 0.2f * v);
        v = l0.y + r0.y; e += a0.y * (v > 0.f ? v : 0.2f * v);
        v = l0.z + r0.z; e += a0.z * (v > 0.f ? v : 0.2f * v);
        v = l0.w + r0.w; e += a0.w * (v > 0.f ? v : 0.2f * v);
        v = l1.x + r1.x; e += a1.x * (v > 0.f ? v : 0.2f * v);
        v = l1.y + r1.y; e += a1.y * (v > 0.f ? v : 0.2f * v);
        v = l1.z + r1.z; e += a1.z * (v > 0.f ? v : 0.2f * v);
        v = l1.w + r1.w; e += a1.w * (v > 0.f ? v : 0.2f * v);
        e += __shfl_xor_sync(0xffffffffu, e, 1);
        e += __shfl_xor_sync(0xffffffffu, e, 2);
        e += __shfl_xor_sync(0xffffffffu, e, 4);

        float mn = fmaxf(m, e);
        float sc = __expf(m - mn);   // 1 if no new max; 0 on first edge
        float p  = __expf(e - mn);
        m = mn;
        s = s * sc + p;
        c0.x = c0.x * sc + p * l0.x;  c0.y = c0.y * sc + p * l0.y;
        c0.z = c0.z * sc + p * l0.z;  c0.w = c0.w * sc + p * l0.w;
        c1.x = c1.x * sc + p * l1.x;  c1.y = c1.y * sc + p * l1.y;
        c1.z = c1.z * sc + p * l1.z;  c1.w = c1.w * sc + p * l1.w;
    }

    float inv = 1.f / (s + 1e-16f);
    c0.x *= inv; c0.y *= inv; c0.z *= inv; c0.w *= inv;
    c1.x *= inv; c1.y *= inv; c1.z *= inv; c1.w *= inv;
    float4* o = (float4*)(agg + (size_t)node * 64) + lane * 2;
    o[0] = c0; o[1] = c1;
}

// ---------------- per-channel sum & sumsq of (v + bias) ---------------------
__global__ void stats64(const float* __restrict__ v,
                        const float* __restrict__ bias,
                        float* __restrict__ st, int N) {
    int t = threadIdx.x;            // 256
    int c = t & 63;
    int r = blockIdx.x * 4 + (t >> 6);
    int stride = gridDim.x * 4;
    float b = bias[c];
    float s = 0.f, q = 0.f;
    for (; r < N; r += stride) {
        float x = v[(size_t)r * 64 + c] + b;
        s += x; q += x * x;
    }
    __shared__ float sh[256], sh2[256];
    sh[t] = s; sh2[t] = q;
    __syncthreads();
    if (t < 64) {
        s = sh[t] + sh[t + 64] + sh[t + 128] + sh[t + 192];
        q = sh2[t] + sh2[t + 64] + sh2[t + 128] + sh2[t + 192];
        atomicAdd(&st[c], s);
        atomicAdd(&st[64 + c], q);
    }
}

// ---------------- BatchNorm (affine) + ReLU ---------------------------------
__global__ void bn_relu(const float* __restrict__ v,
                        const float* __restrict__ bias,
                        const float* __restrict__ st,
                        const float* __restrict__ gamma,
                        const float* __restrict__ beta,
                        float* __restrict__ h, int N) {
    int i = blockIdx.x * blockDim.x + threadIdx.x;
    if (i >= N * 64) return;
    int c = i & 63;
    float invN = 1.f / (float)N;
    float mu = st[c] * invN;
    float var = st[64 + c] * invN - mu * mu;
    float x = (v[i] + bias[c] - mu) * rsqrtf(var + 1e-5f);
    x = x * gamma[c] + beta[c];
    h[i] = fmaxf(x, 0.f);
}

// ---------------- final head: BN(no affine) on [:,:32], softplus [:,32:] ----
__global__ void final_k(const float* __restrict__ v,
                        const float* __restrict__ bias,
                        const float* __restrict__ st,
                        float* __restrict__ out, int N) {
    int i = blockIdx.x * blockDim.x + threadIdx.x;
    if (i >= N * 64) return;
    int n = i >> 6, c = i & 63;
    float x = v[i] + bias[c];
    if (c < 32) {
        float invN = 1.f / (float)N;
        float mu = st[c] * invN;
        float var = st[64 + c] * invN - mu * mu;
        out[(size_t)n * 32 + c] = (x - mu) * rsqrtf(var + 1e-5f);
    } else {
        float sp = fmaxf(x, 0.f) + log1pf(expf(-fabsf(x)));
        out[(size_t)N * 32 + (size_t)n * 32 + (c - 32)] = sp;
    }
}

// ---------------- host launcher ---------------------------------------------
extern "C" void kernel_launch(void* const* d_in, const int* in_sizes, int n_in,
                              void* d_out, int out_size) {
    const float* x    = (const float*)d_in[0];
    const void*  ei   = d_in[1];
    const float* Wl1  = (const float*)d_in[2];
    const float* Wr1  = (const float*)d_in[3];
    const float* att1 = (const float*)d_in[4];
    const float* b1   = (const float*)d_in[5];
    const float* ga1  = (const float*)d_in[6];
    const float* be1  = (const float*)d_in[7];
    const float* Wl2  = (const float*)d_in[8];
    const float* Wr2  = (const float*)d_in[9];
    const float* att2 = (const float*)d_in[10];
    const float* b2   = (const float*)d_in[11];
    float* out = (float*)d_out;

    const int N  = in_sizes[0] / 128;   // 50000
    const int E  = in_sizes[1] / 2;     // 800000
    const int EE = E + N;               // + self loops
    const int nAgg = N * 64;

    float *p_xl, *p_xr, *p_agg, *p_h, *p_st;
    int *p_srcb, *p_off, *p_deg, *p_cur;
    cudaGetSymbolAddress((void**)&p_xl,   g_xl);
    cudaGetSymbolAddress((void**)&p_xr,   g_xr);
    cudaGetSymbolAddress((void**)&p_agg,  g_agg);
    cudaGetSymbolAddress((void**)&p_h,    g_h);
    cudaGetSymbolAddress((void**)&p_st,   g_st);
    cudaGetSymbolAddress((void**)&p_srcb, g_srcb);
    cudaGetSymbolAddress((void**)&p_off,  g_off);
    cudaGetSymbolAddress((void**)&p_deg,  g_deg);
    cudaGetSymbolAddress((void**)&p_cur,  g_cur);

    const int TB = 256;
    const int gEdge = (EE + TB - 1) / TB;
    const int gGemm = (N + 127) / 128;
    const int gFuse = (N * 8 + TB - 1) / TB;
    const int gElem = (nAgg + TB - 1) / TB;

    // ---- CSR build (shared by both layers) ----
    detect_k<<<1, 32>>>((const int*)ei, E);
    cudaMemsetAsync(p_deg, 0, (size_t)N * sizeof(int));
    hist_k<<<gEdge, TB>>>(ei, p_deg, E, EE);
    scan_k<<<1, 1024>>>(p_deg, p_off, p_cur, N);
    scatter_k<<<gEdge, TB>>>(ei, p_cur, p_srcb, E, EE);

    // ---- layer 1 ----
    gemm_dual<<<gGemm, TB>>>(x, Wl1, Wr1, p_xl, p_xr, N, 128);
    gat_fused<<<gFuse, TB>>>(p_srcb, p_off, p_deg, p_xl, p_xr, att1, p_agg, N);
    cudaMemsetAsync(p_st, 0, 128 * sizeof(float));
    stats64<<<256, TB>>>(p_agg, b1, p_st, N);
    bn_relu<<<gElem, TB>>>(p_agg, b1, p_st, ga1, be1, p_h, N);

    // ---- layer 2 ----
    gemm_dual<<<gGemm, TB>>>(p_h, Wl2, Wr2, p_xl, p_xr, N, 64);
    gat_fused<<<gFuse, TB>>>(p_srcb, p_off, p_deg, p_xl, p_xr, att2, p_agg, N);
    cudaMemsetAsync(p_st, 0, 128 * sizeof(float));
    stats64<<<256, TB>>>(p_agg, b2, p_st, N);
    final_k<<<gElem, TB>>>(p_agg, b2, p_st, out, N);
}

// round 6
// speedup vs baseline: 1.8105x; 1.1046x over previous
#include <cuda_runtime.h>
#include <math.h>
#include <stdint.h>

// Problem constants (shapes fixed by the dataset)
#define NNODES 50000
#define NEDGES 800000
#define EETOT  (NNODES + NEDGES)
#define C64    64

// ---------------- scratch (static device globals; no allocation allowed) ---
__device__ __align__(256) float g_xl [NNODES * C64];
__device__ __align__(256) float g_xr [NNODES * C64];
__device__ __align__(256) float g_agg[NNODES * C64];
__device__ __align__(256) int   g_srcb[EETOT];      // CSR src ids (sorted by dst)
__device__ __align__(256) int   g_off [NNODES];     // CSR row offsets
__device__ __align__(256) int   g_deg [NNODES];     // in-degree per node
__device__ __align__(256) int   g_cur [NNODES];     // scatter cursors
__device__ __align__(256) float g_st [128];         // per-channel sum / sumsq
__device__ __align__(256) float g_bnp[128];         // BN scale / shift
__device__ int g_idx64;                              // 1 if edge_index is int64

// ---------------- helpers ---------------------------------------------------
__device__ __forceinline__ int load_idx(const void* ei, long long pos) {
    if (g_idx64) return (int)((const long long*)ei)[pos];
    return ((const int*)ei)[pos];
}

__global__ void detect_k(const int* ei32, int E) {
    int t = threadIdx.x;  // 32 threads
    int nz = 0;
    if (2 * t + 1 < 2 * E)        nz |= (ei32[2 * t + 1] != 0);
    if (2 * (t + 32) + 1 < 2 * E) nz |= (ei32[2 * (t + 32) + 1] != 0);
    nz = __any_sync(0xffffffffu, nz);
    if (t == 0) g_idx64 = nz ? 0 : 1;
}

// ---------------- CSR build: histogram, scan, scatter ------------------------
__global__ void hist_k(const void* __restrict__ ei, int* __restrict__ deg,
                       int E, int EE) {
    int i = blockIdx.x * blockDim.x + threadIdx.x;
    if (i >= EE) return;
    int dst = (i < E) ? load_idx(ei, (long long)E + i) : i - E;
    atomicAdd(&deg[dst], 1);
}

__global__ void scan_k(const int* __restrict__ deg, int* __restrict__ off,
                       int* __restrict__ cur, float* __restrict__ st, int N) {
    __shared__ int part[1024];
    int t = threadIdx.x;                 // 1024 threads, 1 block
    if (t < 128) st[t] = 0.f;            // zero BN stats for layer 1
    int chunk = (N + 1023) >> 10;
    int lo = t * chunk;
    int hi = lo + chunk; if (hi > N) hi = N;
    int s = 0;
    for (int i = lo; i < hi; ++i) s += deg[i];
    part[t] = s;
    __syncthreads();
    for (int d = 1; d < 1024; d <<= 1) {
        int u = (t >= d) ? part[t - d] : 0;
        __syncthreads();
        part[t] += u;
        __syncthreads();
    }
    int run = part[t] - s;               // exclusive prefix of this chunk
    for (int i = lo; i < hi; ++i) {
        off[i] = run; cur[i] = run;
        run += deg[i];
    }
}

__global__ void scatter_k(const void* __restrict__ ei, int* __restrict__ cur,
                          int* __restrict__ srcb, int E, int EE) {
    int i = blockIdx.x * blockDim.x + threadIdx.x;
    if (i >= EE) return;
    int src, dst;
    if (i < E) { src = load_idx(ei, i); dst = load_idx(ei, (long long)E + i); }
    else       { src = dst = i - E; }
    int pos = atomicAdd(&cur[dst], 1);
    srcb[pos] = src;
}

// ---------------- dual GEMM: O0 = A @ W0, O1 = A @ W1 ----------------------
// A: M x K (K in {64,128}), W0/W1: K x 64 row-major, O0/O1: M x 64.
// 128x128 tile, Kc=32, 256 threads, 8x8 micro-tile, transposed As so both
// operands come in as conflict-free LDS.128. Optional fused BN+ReLU on A
// (x = max(a*scale[k]+shift[k],0)) applied during staging.
__global__ void gemm_dual(const float* __restrict__ A,
                          const float* __restrict__ W0,
                          const float* __restrict__ W1,
                          const float* __restrict__ bnp,   // null = no BN
                          float* __restrict__ O0, float* __restrict__ O1,
                          int M, int K) {
    __shared__ float As[32][132];   // [k][row] + pad
    __shared__ float Ws[32][128];   // [k][W0cols | W1cols]
    const int t  = threadIdx.x;
    const int tx = t & 15;
    const int ty = t >> 4;
    const int row0 = blockIdx.x * 128;
    const int nk = K >> 5;

    float acc[8][8];
#pragma unroll
    for (int i = 0; i < 8; ++i)
#pragma unroll
        for (int j = 0; j < 8; ++j) acc[i][j] = 0.f;

    float4 av[4], wv[4];

    // ---- prefetch tile 0 into registers ----
#pragma unroll
    for (int i = 0; i < 4; ++i) {
        int l = t + 256 * i;
        int r = l >> 3, kq = l & 7;
        float4 v = make_float4(0.f, 0.f, 0.f, 0.f);
        if (row0 + r < M)
            v = *(const float4*)&A[(size_t)(row0 + r) * K + kq * 4];
        if (bnp) {
            float4 sc = *(const float4*)&bnp[kq * 4];
            float4 sh = *(const float4*)&bnp[64 + kq * 4];
            v.x = fmaxf(v.x * sc.x + sh.x, 0.f);
            v.y = fmaxf(v.y * sc.y + sh.y, 0.f);
            v.z = fmaxf(v.z * sc.z + sh.z, 0.f);
            v.w = fmaxf(v.w * sc.w + sh.w, 0.f);
        }
        av[i] = v;
    }
#pragma unroll
    for (int i = 0; i < 4; ++i) {
        int l = t + 256 * i;
        int kk = l >> 5, c = (l & 31) * 4;
        wv[i] = (c < 64) ? *(const float4*)&W0[(size_t)kk * 64 + c]
                         : *(const float4*)&W1[(size_t)kk * 64 + (c - 64)];
    }

    for (int kt = 0; kt < nk; ++kt) {
        __syncthreads();   // previous compute done before overwriting smem
        // ---- store staged registers to smem ----
#pragma unroll
        for (int i = 0; i < 4; ++i) {
            int l = t + 256 * i;
            int r = l >> 3, kq = l & 7;
            As[kq * 4 + 0][r] = av[i].x;
            As[kq * 4 + 1][r] = av[i].y;
            As[kq * 4 + 2][r] = av[i].z;
            As[kq * 4 + 3][r] = av[i].w;
        }
#pragma unroll
        for (int i = 0; i < 4; ++i) {
            int l = t + 256 * i;
            int kk = l >> 5, c = (l & 31) * 4;
            *(float4*)&Ws[kk][c] = wv[i];
        }
        __syncthreads();

        // ---- prefetch next tile while computing ----
        if (kt + 1 < nk) {
            int k0 = (kt + 1) * 32;
#pragma unroll
            for (int i = 0; i < 4; ++i) {
                int l = t + 256 * i;
                int r = l >> 3, kq = l & 7;
                float4 v = make_float4(0.f, 0.f, 0.f, 0.f);
                if (row0 + r < M)
                    v = *(const float4*)&A[(size_t)(row0 + r) * K + k0 + kq * 4];
                if (bnp) {
                    float4 sc = *(const float4*)&bnp[k0 + kq * 4];
                    float4 sh = *(const float4*)&bnp[64 + k0 + kq * 4];
                    v.x = fmaxf(v.x * sc.x + sh.x, 0.f);
                    v.y = fmaxf(v.y * sc.y + sh.y, 0.f);
                    v.z = fmaxf(v.z * sc.z + sh.z, 0.f);
                    v.w = fmaxf(v.w * sc.w + sh.w, 0.f);
                }
                av[i] = v;
            }
#pragma unroll
            for (int i = 0; i < 4; ++i) {
                int l = t + 256 * i;
                int kk = l >> 5, c = (l & 31) * 4;
                wv[i] = (c < 64)
                    ? *(const float4*)&W0[(size_t)(k0 + kk) * 64 + c]
                    : *(const float4*)&W1[(size_t)(k0 + kk) * 64 + (c - 64)];
            }
        }

#pragma unroll 8
        for (int k = 0; k < 32; ++k) {
            float4 a0 = *(const float4*)&As[k][ty * 8];
            float4 a1 = *(const float4*)&As[k][ty * 8 + 4];
            float4 b0 = *(const float4*)&Ws[k][tx * 4];        // W0 cols
            float4 b1 = *(const float4*)&Ws[k][64 + tx * 4];   // W1 cols
            float a8[8] = {a0.x, a0.y, a0.z, a0.w, a1.x, a1.y, a1.z, a1.w};
            float b8[8] = {b0.x, b0.y, b0.z, b0.w, b1.x, b1.y, b1.z, b1.w};
#pragma unroll
            for (int i = 0; i < 8; ++i)
#pragma unroll
                for (int j = 0; j < 8; ++j) acc[i][j] += a8[i] * b8[j];
        }
    }

#pragma unroll
    for (int i = 0; i < 8; ++i) {
        int r = row0 + ty * 8 + i;
        if (r < M) {
            *(float4*)&O0[(size_t)r * 64 + tx * 4] =
                make_float4(acc[i][0], acc[i][1], acc[i][2], acc[i][3]);
            *(float4*)&O1[(size_t)r * 64 + tx * 4] =
                make_float4(acc[i][4], acc[i][5], acc[i][6], acc[i][7]);
        }
    }
}

// ---------------- fused GATv2 edge pass (node-parallel, online softmax) -----
// 4 lanes per dst node, each lane owns 16 channels (4 float4).
// Per edge: e = att . leakyrelu(xl[src] + xr[dst]) via 2-stage butterfly over
// the node's OWN 4-lane group (group mask — lanes of a group share the same
// trip count, so masked shuffles in the divergent loop are legal).
// Online softmax with rescale; next edge's src row prefetched.
// Epilogue adds bias, writes agg, and accumulates BN stats (sum, sumsq).
__global__ void gat_fused(const int* __restrict__ srcb,
                          const int* __restrict__ off,
                          const int* __restrict__ deg,
                          const float* __restrict__ xl,
                          const float* __restrict__ xr,
                          const float* __restrict__ att,
                          const float* __restrict__ bias,
                          float* __restrict__ agg,
                          float* __restrict__ st, int N) {
    __shared__ float ssum[64], ssq[64];
    const int t = threadIdx.x;
    int g = blockIdx.x * blockDim.x + t;
    int node = g >> 2;
    int lane = g & 3;
    bool valid = node < N;
    int nd = valid ? node : 0;

    // group mask: the 4 lanes of this node within the warp
    const unsigned gmask = 0xFu << ((t & 31) & ~3);

    if (t < 64) { ssum[t] = 0.f; ssq[t] = 0.f; }

    const float4* xr4 = (const float4*)(xr + (size_t)nd * 64) + lane * 4;
    float4 r0 = xr4[0], r1 = xr4[1], r2 = xr4[2], r3 = xr4[3];
    const float4* at4 = (const float4*)att + lane * 4;
    float4 a0 = at4[0], a1 = at4[1], a2 = at4[2], a3 = at4[3];

    int base = valid ? off[nd] : 0;
    int cnt  = valid ? deg[nd] : 0;

    float m = -1e30f, s = 0.f;
    float4 c0 = make_float4(0.f,0.f,0.f,0.f), c1 = c0, c2 = c0, c3 = c0;
    float4 l0, l1, l2, l3;

    if (cnt > 0) {
        int src = __ldg(&srcb[base]);
        const float4* p = (const float4*)(xl + (size_t)src * 64) + lane * 4;
        l0 = p[0]; l1 = p[1]; l2 = p[2]; l3 = p[3];
    }

    for (int j = 0; j < cnt; ++j) {
        float4 n0, n1, n2, n3;
        bool more = (j + 1 < cnt);
        if (more) {
            int ns = __ldg(&srcb[base + j + 1]);
            const float4* p = (const float4*)(xl + (size_t)ns * 64) + lane * 4;
            n0 = p[0]; n1 = p[1]; n2 = p[2]; n3 = p[3];
        }

        float e = 0.f, v;
#define EQ(L, R, A) \
        v = L.x + R.x; e += A.x * fmaxf(v, 0.2f * v); \
        v = L.y + R.y; e += A.y * fmaxf(v, 0.2f * v); \
        v = L.z + R.z; e += A.z * fmaxf(v, 0.2f * v); \
        v = L.w + R.w; e += A.w * fmaxf(v, 0.2f * v);
        EQ(l0, r0, a0) EQ(l1, r1, a1) EQ(l2, r2, a2) EQ(l3, r3, a3)
#undef EQ
        e += __shfl_xor_sync(gmask, e, 1);
        e += __shfl_xor_sync(gmask, e, 2);

        float mn = fmaxf(m, e);
        float sc = __expf(m - mn);
        float p  = __expf(e - mn);
        m = mn;
        s = s * sc + p;
#define AQ(C, L) \
        C.x = C.x * sc + p * L.x; C.y = C.y * sc + p * L.y; \
        C.z = C.z * sc + p * L.z; C.w = C.w * sc + p * L.w;
        AQ(c0, l0) AQ(c1, l1) AQ(c2, l2) AQ(c3, l3)
#undef AQ
        if (more) { l0 = n0; l1 = n1; l2 = n2; l3 = n3; }
    }

    float inv = 1.f / (s + 1e-16f);
    const float4* bq = (const float4*)bias + lane * 4;
    float4 b0 = bq[0], b1 = bq[1], b2 = bq[2], b3 = bq[3];
    float x[16];
#define XQ(q, C, B) \
    x[4*q+0] = C.x * inv + B.x; x[4*q+1] = C.y * inv + B.y; \
    x[4*q+2] = C.z * inv + B.z; x[4*q+3] = C.w * inv + B.w;
    XQ(0, c0, b0) XQ(1, c1, b1) XQ(2, c2, b2) XQ(3, c3, b3)
#undef XQ

    if (valid) {
        float4* o = (float4*)(agg + (size_t)node * 64) + lane * 4;
        o[0] = make_float4(x[0],  x[1],  x[2],  x[3]);
        o[1] = make_float4(x[4],  x[5],  x[6],  x[7]);
        o[2] = make_float4(x[8],  x[9],  x[10], x[11]);
        o[3] = make_float4(x[12], x[13], x[14], x[15]);
    }
    if (!valid) {
#pragma unroll
        for (int i = 0; i < 16; ++i) x[i] = 0.f;
    }

    // BN stats: reduce over the 8 nodes of this warp (full convergence here),
    // then smem, then global.
    __syncthreads();   // ssum/ssq zero-init visible
#pragma unroll
    for (int i = 0; i < 16; ++i) {
        float sv = x[i];
        float qv = x[i] * x[i];
        sv += __shfl_down_sync(0xffffffffu, sv, 16);
        sv += __shfl_down_sync(0xffffffffu, sv, 8);
        sv += __shfl_down_sync(0xffffffffu, sv, 4);
        qv += __shfl_down_sync(0xffffffffu, qv, 16);
        qv += __shfl_down_sync(0xffffffffu, qv, 8);
        qv += __shfl_down_sync(0xffffffffu, qv, 4);
        if ((t & 31) < 4) {
            int ch = lane * 16 + i;
            atomicAdd(&ssum[ch], sv);
            atomicAdd(&ssq[ch], qv);
        }
    }
    __syncthreads();
    if (t < 64) {
        atomicAdd(&st[t], ssum[t]);
        atomicAdd(&st[64 + t], ssq[t]);
    }
}

// ---------------- BN prep: st -> (scale, shift); zero st for next layer -----
__global__ void prep_bn(const float* __restrict__ st,
                        const float* __restrict__ gamma,
                        const float* __restrict__ beta,
                        float* __restrict__ bnp,
                        float* __restrict__ st_mut, int N) {
    int t = threadIdx.x;   // 128 threads, 1 block
    float scale = 0.f, shift = 0.f;
    if (t < 64) {
        float invN = 1.f / (float)N;
        float mu  = st[t] * invN;
        float var = st[64 + t] * invN - mu * mu;
        float rs  = rsqrtf(var + 1e-5f);
        scale = gamma[t] * rs;
        shift = beta[t] - mu * scale;
    }
    __syncthreads();       // reads done before zeroing
    if (t < 64) { bnp[t] = scale; bnp[64 + t] = shift; }
    st_mut[t] = 0.f;
}

// ---------------- final head: BN(no affine) on [:,:32], softplus [:,32:] ----
// v already includes bias.
__global__ void final_k(const float* __restrict__ v,
                        const float* __restrict__ st,
                        float* __restrict__ out, int N) {
    int i = blockIdx.x * blockDim.x + threadIdx.x;
    if (i >= N * 64) return;
    int n = i >> 6, c = i & 63;
    float x = v[i];
    if (c < 32) {
        float invN = 1.f / (float)N;
        float mu = st[c] * invN;
        float var = st[64 + c] * invN - mu * mu;
        out[(size_t)n * 32 + c] = (x - mu) * rsqrtf(var + 1e-5f);
    } else {
        float sp = fmaxf(x, 0.f) + log1pf(expf(-fabsf(x)));
        out[(size_t)N * 32 + (size_t)n * 32 + (c - 32)] = sp;
    }
}

// ---------------- host launcher ---------------------------------------------
extern "C" void kernel_launch(void* const* d_in, const int* in_sizes, int n_in,
                              void* d_out, int out_size) {
    const float* x    = (const float*)d_in[0];
    const void*  ei   = d_in[1];
    const float* Wl1  = (const float*)d_in[2];
    const float* Wr1  = (const float*)d_in[3];
    const float* att1 = (const float*)d_in[4];
    const float* b1   = (const float*)d_in[5];
    const float* ga1  = (const float*)d_in[6];
    const float* be1  = (const float*)d_in[7];
    const float* Wl2  = (const float*)d_in[8];
    const float* Wr2  = (const float*)d_in[9];
    const float* att2 = (const float*)d_in[10];
    const float* b2   = (const float*)d_in[11];
    float* out = (float*)d_out;

    const int N  = in_sizes[0] / 128;   // 50000
    const int E  = in_sizes[1] / 2;     // 800000
    const int EE = E + N;               // + self loops

    float *p_xl, *p_xr, *p_agg, *p_st, *p_bnp;
    int *p_srcb, *p_off, *p_deg, *p_cur;
    cudaGetSymbolAddress((void**)&p_xl,   g_xl);
    cudaGetSymbolAddress((void**)&p_xr,   g_xr);
    cudaGetSymbolAddress((void**)&p_agg,  g_agg);
    cudaGetSymbolAddress((void**)&p_st,   g_st);
    cudaGetSymbolAddress((void**)&p_bnp,  g_bnp);
    cudaGetSymbolAddress((void**)&p_srcb, g_srcb);
    cudaGetSymbolAddress((void**)&p_off,  g_off);
    cudaGetSymbolAddress((void**)&p_deg,  g_deg);
    cudaGetSymbolAddress((void**)&p_cur,  g_cur);

    const int TB = 256;
    const int gEdge = (EE + TB - 1) / TB;
    const int gGemm = (N + 127) / 128;
    const int gFuse = (N * 4 + TB - 1) / TB;
    const int gElem = (N * 64 + TB - 1) / TB;

    // ---- CSR build (shared by both layers) ----
    detect_k<<<1, 32>>>((const int*)ei, E);
    cudaMemsetAsync(p_deg, 0, (size_t)N * sizeof(int));
    hist_k<<<gEdge, TB>>>(ei, p_deg, E, EE);
    scan_k<<<1, 1024>>>(p_deg, p_off, p_cur, p_st, N);
    scatter_k<<<gEdge, TB>>>(ei, p_cur, p_srcb, E, EE);

    // ---- layer 1 ----
    gemm_dual<<<gGemm, TB>>>(x, Wl1, Wr1, nullptr, p_xl, p_xr, N, 128);
    gat_fused<<<gFuse, TB>>>(p_srcb, p_off, p_deg, p_xl, p_xr, att1, b1,
                             p_agg, p_st, N);
    prep_bn<<<1, 128>>>(p_st, ga1, be1, p_bnp, p_st, N);

    // ---- layer 2 (BN+ReLU fused into gemm A-staging) ----
    gemm_dual<<<gGemm, TB>>>(p_agg, Wl2, Wr2, p_bnp, p_xl, p_xr, N, 64);
    gat_fused<<<gFuse, TB>>>(p_srcb, p_off, p_deg, p_xl, p_xr, att2, b2,
                             p_agg, p_st, N);
    final_k<<<gElem, TB>>>(p_agg, p_st, out, N);
}

// round 7
// speedup vs baseline: 2.2763x; 1.2573x over previous
#include <cuda_runtime.h>
#include <math.h>
#include <stdint.h>

// Problem constants (shapes fixed by the dataset)
#define NNODES 50000
#define NEDGES 800000
#define EETOT  (NNODES + NEDGES)
#define C64    64

// ---------------- scratch (static device globals; no allocation allowed) ---
__device__ __align__(256) float g_xl [NNODES * C64];
__device__ __align__(256) float g_xr [NNODES * C64];
__device__ __align__(256) float g_agg[NNODES * C64];
__device__ __align__(256) int   g_srcb[EETOT];      // CSR src ids (sorted by dst)
__device__ __align__(256) int   g_off [NNODES];     // CSR row offsets
__device__ __align__(256) int   g_deg [NNODES];     // in-degree per node
__device__ __align__(256) int   g_cur [NNODES];     // scatter cursors
__device__ __align__(256) int   g_bsum[64];         // per-block degree sums
__device__ __align__(256) int   g_bofs[64];         // exclusive scan of bsum
__device__ __align__(256) float g_st [128];         // per-channel sum / sumsq
__device__ __align__(256) float g_bnp[128];         // BN scale / shift
__device__ int g_idx64;                              // 1 if edge_index is int64

// ---------------- helpers ---------------------------------------------------
__device__ __forceinline__ int load_idx(const void* ei, long long pos) {
    if (g_idx64) return (int)((const long long*)ei)[pos];
    return ((const int*)ei)[pos];
}

__device__ __forceinline__ float tf32r(float x) {
    uint32_t u;
    asm("cvt.rna.tf32.f32 %0, %1;" : "=r"(u) : "f"(x));
    return __uint_as_float(u);
}

#define MMA_TF32(d, a, b0, b1) \
    asm volatile("mma.sync.aligned.m16n8k8.row.col.f32.tf32.tf32.f32 " \
                 "{%0,%1,%2,%3}, {%4,%5,%6,%7}, {%8,%9}, {%0,%1,%2,%3};" \
                 : "+f"((d)[0]), "+f"((d)[1]), "+f"((d)[2]), "+f"((d)[3]) \
                 : "r"((a)[0]), "r"((a)[1]), "r"((a)[2]), "r"((a)[3]), \
                   "r"(b0), "r"(b1))

__global__ void detect_k(const int* ei32, int E) {
    int t = threadIdx.x;  // 32 threads
    int nz = 0;
    if (2 * t + 1 < 2 * E)        nz |= (ei32[2 * t + 1] != 0);
    if (2 * (t + 32) + 1 < 2 * E) nz |= (ei32[2 * (t + 32) + 1] != 0);
    nz = __any_sync(0xffffffffu, nz);
    if (t == 0) g_idx64 = nz ? 0 : 1;
}

// ---------------- CSR build: histogram, 3-stage scan, scatter ---------------
__global__ void hist_k(const void* __restrict__ ei, int* __restrict__ deg,
                       int E, int EE) {
    int i = blockIdx.x * blockDim.x + threadIdx.x;
    if (i >= EE) return;
    int dst = (i < E) ? load_idx(ei, (long long)E + i) : i - E;
    atomicAdd(&deg[dst], 1);
}

// per-block (1024 nodes) degree sums
__global__ void blocksum_k(const int* __restrict__ deg, int* __restrict__ bsum,
                           int N) {
    __shared__ int ws[8];
    int t = threadIdx.x;                 // 256
    int i0 = blockIdx.x * 1024 + t * 4;
    int s = 0;
    if (i0 + 3 < N) {
        int4 v = *(const int4*)&deg[i0];
        s = v.x + v.y + v.z + v.w;
    } else {
        for (int j = 0; j < 4; ++j) if (i0 + j < N) s += deg[i0 + j];
    }
#pragma unroll
    for (int o = 16; o; o >>= 1) s += __shfl_down_sync(0xffffffffu, s, o);
    if ((t & 31) == 0) ws[t >> 5] = s;
    __syncthreads();
    if (t == 0) {
        int tot = 0;
#pragma unroll
        for (int i = 0; i < 8; ++i) tot += ws[i];
        bsum[blockIdx.x] = tot;
    }
}

// exclusive scan of ≤64 block sums; also zero BN stats for layer 1
__global__ void topscan_k(const int* __restrict__ bsum, int* __restrict__ bofs,
                          float* __restrict__ st, int nb) {
    int t = threadIdx.x;                 // 128
    st[t] = 0.f;
    __shared__ int sh[64];
    if (t < 64) {
        int lane = t & 31;
        int v = (t < nb) ? bsum[t] : 0;
        int inc = v;
#pragma unroll
        for (int o = 1; o < 32; o <<= 1) {
            int u = __shfl_up_sync(0xffffffffu, inc, o);
            if (lane >= o) inc += u;
        }
        sh[t] = inc;
    }
    __syncthreads();
    if (t < 64) {
        int add = (t >= 32) ? sh[31] : 0;
        int inc = sh[t] + add;
        int v = (t < nb) ? bsum[t] : 0;
        bofs[t] = inc - v;
    }
}

// per-block fill of off/cur via hierarchical scan
__global__ void fill_k(const int* __restrict__ deg, const int* __restrict__ bofs,
                       int* __restrict__ off, int* __restrict__ cur, int N) {
    __shared__ int wsum[8];
    int t = threadIdx.x, lane = t & 31, warp = t >> 5;
    int i0 = blockIdx.x * 1024 + t * 4;
    int d0 = 0, d1 = 0, d2 = 0, d3 = 0;
    if (i0 + 3 < N) {
        int4 v = *(const int4*)&deg[i0];
        d0 = v.x; d1 = v.y; d2 = v.z; d3 = v.w;
    } else {
        if (i0     < N) d0 = deg[i0];
        if (i0 + 1 < N) d1 = deg[i0 + 1];
        if (i0 + 2 < N) d2 = deg[i0 + 2];
    }
    int tsum = d0 + d1 + d2 + d3;
    int inc = tsum;
#pragma unroll
    for (int o = 1; o < 32; o <<= 1) {
        int u = __shfl_up_sync(0xffffffffu, inc, o);
        if (lane >= o) inc += u;
    }
    if (lane == 31) wsum[warp] = inc;
    __syncthreads();
    int wofs = 0;
#pragma unroll
    for (int wi = 0; wi < 8; ++wi) if (wi < warp) wofs += wsum[wi];
    int base = bofs[blockIdx.x] + wofs + inc - tsum;
    int o0 = base, o1 = o0 + d0, o2 = o1 + d1, o3 = o2 + d2;
    if (i0 + 3 < N) {
        *(int4*)&off[i0] = make_int4(o0, o1, o2, o3);
        *(int4*)&cur[i0] = make_int4(o0, o1, o2, o3);
    } else {
        if (i0     < N) { off[i0]     = o0; cur[i0]     = o0; }
        if (i0 + 1 < N) { off[i0 + 1] = o1; cur[i0 + 1] = o1; }
        if (i0 + 2 < N) { off[i0 + 2] = o2; cur[i0 + 2] = o2; }
    }
}

__global__ void scatter_k(const void* __restrict__ ei, int* __restrict__ cur,
                          int* __restrict__ srcb, int E, int EE) {
    int i = blockIdx.x * blockDim.x + threadIdx.x;
    if (i >= EE) return;
    int src, dst;
    if (i < E) { src = load_idx(ei, i); dst = load_idx(ei, (long long)E + i); }
    else       { src = dst = i - E; }
    int pos = atomicAdd(&cur[dst], 1);
    srcb[pos] = src;
}

// ---------------- dual GEMM via tf32x3 tensor cores -------------------------
// O0 = A @ W0, O1 = A @ W1.  A: M x K, W: K x 64 row-major.
// 128x128 block tile (cols = [W0|W1]), 8 warps: 4(m) x 2(n), each warp
// 32 rows x 64 cols = 2 m-tiles x 8 n-tiles of m16n8k8.
// Operands split hi/lo (tf32x3, 3 mma per tile-k): error ~O(eps_tf32^2).
// Optional fused BN+ReLU on A during staging.
#define KC 16
__global__ void __launch_bounds__(256)
gemm_tf32(const float* __restrict__ A,
          const float* __restrict__ W0,
          const float* __restrict__ W1,
          const float* __restrict__ bnp,   // null = no BN
          float* __restrict__ O0, float* __restrict__ O1,
          int M, int K) {
    __shared__ uint32_t Ah[KC][136], Al[KC][136];   // [k][row], pad->8-bank shift
    __shared__ uint32_t Wh[KC][136], Wl[KC][136];   // [k][col]
    const int t = threadIdx.x;
    const int lane = t & 31, warp = t >> 5;
    const int wm = warp >> 1, wn = warp & 1;
    const int g = lane >> 2, c = lane & 3;
    const int row0 = blockIdx.x * 128;
    const int rbase = wm * 32;
    const int nbase0 = wn * 64;

    float d[2][8][4];
#pragma unroll
    for (int i = 0; i < 2; ++i)
#pragma unroll
        for (int j = 0; j < 8; ++j)
#pragma unroll
            for (int q = 0; q < 4; ++q) d[i][j][q] = 0.f;

    const int nchunk = K / KC;
    for (int ch = 0; ch < nchunk; ++ch) {
        const int k0 = ch * KC;
        __syncthreads();
        // ---- stage A: 128 rows x 16 k, hi/lo split, transposed [k][row] ----
#pragma unroll
        for (int i = 0; i < 2; ++i) {
            int l = t + 256 * i;          // 0..511
            int r = l >> 2, kq = (l & 3) * 4;
            float4 v = make_float4(0.f, 0.f, 0.f, 0.f);
            if (row0 + r < M)
                v = *(const float4*)&A[(size_t)(row0 + r) * K + k0 + kq];
            if (bnp) {
                float4 sc = *(const float4*)&bnp[k0 + kq];
                float4 sh = *(const float4*)&bnp[64 + k0 + kq];
                v.x = fmaxf(v.x * sc.x + sh.x, 0.f);
                v.y = fmaxf(v.y * sc.y + sh.y, 0.f);
                v.z = fmaxf(v.z * sc.z + sh.z, 0.f);
                v.w = fmaxf(v.w * sc.w + sh.w, 0.f);
            }
            float vv[4] = {v.x, v.y, v.z, v.w};
#pragma unroll
            for (int j = 0; j < 4; ++j) {
                float hi = tf32r(vv[j]);
                float lo = tf32r(vv[j] - hi);
                Ah[kq + j][r] = __float_as_uint(hi);
                Al[kq + j][r] = __float_as_uint(lo);
            }
        }
        // ---- stage W: 16 k x [W0 | W1], hi/lo split ----
#pragma unroll
        for (int i = 0; i < 2; ++i) {
            int l = t + 256 * i;
            int kk = l >> 5, col = (l & 31) * 4;
            const float* src = (col < 64)
                ? &W0[(size_t)(k0 + kk) * 64 + col]
                : &W1[(size_t)(k0 + kk) * 64 + (col - 64)];
            float4 v = *(const float4*)src;
            float vv[4] = {v.x, v.y, v.z, v.w};
#pragma unroll
            for (int j = 0; j < 4; ++j) {
                float hi = tf32r(vv[j]);
                float lo = tf32r(vv[j] - hi);
                Wh[kk][col + j] = __float_as_uint(hi);
                Wl[kk][col + j] = __float_as_uint(lo);
            }
        }
        __syncthreads();

        // ---- compute: KC/8 k-steps ----
#pragma unroll
        for (int ks = 0; ks < KC / 8; ++ks) {
            const int kb = ks * 8;
            uint32_t ah[2][4], al[2][4];
#pragma unroll
            for (int mt = 0; mt < 2; ++mt) {
                int r = rbase + mt * 16 + g;
                ah[mt][0] = Ah[kb + c][r];     ah[mt][1] = Ah[kb + c][r + 8];
                ah[mt][2] = Ah[kb + c + 4][r]; ah[mt][3] = Ah[kb + c + 4][r + 8];
                al[mt][0] = Al[kb + c][r];     al[mt][1] = Al[kb + c][r + 8];
                al[mt][2] = Al[kb + c + 4][r]; al[mt][3] = Al[kb + c + 4][r + 8];
            }
#pragma unroll
            for (int nt = 0; nt < 8; ++nt) {
                int n = nbase0 + nt * 8 + g;
                uint32_t bh0 = Wh[kb + c][n],     bh1 = Wh[kb + c + 4][n];
                uint32_t bl0 = Wl[kb + c][n],     bl1 = Wl[kb + c + 4][n];
#pragma unroll
                for (int mt = 0; mt < 2; ++mt) {
                    MMA_TF32(d[mt][nt], ah[mt], bh0, bh1);
                    MMA_TF32(d[mt][nt], ah[mt], bl0, bl1);
                    MMA_TF32(d[mt][nt], al[mt], bh0, bh1);
                }
            }
        }
    }

    // ---- epilogue: warp's cols all in O0 (wn=0) or O1 (wn=1) ----
    float* O = (wn == 0) ? O0 : O1;
#pragma unroll
    for (int mt = 0; mt < 2; ++mt) {
#pragma unroll
        for (int nt = 0; nt < 8; ++nt) {
            int nn = nt * 8 + 2 * c;           // col within 0..63
            int r0w = row0 + rbase + mt * 16 + g;
            if (r0w < M)
                *(float2*)&O[(size_t)r0w * 64 + nn] =
                    make_float2(d[mt][nt][0], d[mt][nt][1]);
            int r1w = r0w + 8;
            if (r1w < M)
                *(float2*)&O[(size_t)r1w * 64 + nn] =
                    make_float2(d[mt][nt][2], d[mt][nt][3]);
        }
    }
}

// ---------------- fused GATv2 edge pass (node-parallel, online softmax) -----
__global__ void gat_fused(const int* __restrict__ srcb,
                          const int* __restrict__ off,
                          const int* __restrict__ deg,
                          const float* __restrict__ xl,
                          const float* __restrict__ xr,
                          const float* __restrict__ att,
                          const float* __restrict__ bias,
                          float* __restrict__ agg,
                          float* __restrict__ st, int N) {
    __shared__ float ssum[64], ssq[64];
    const int t = threadIdx.x;
    int g = blockIdx.x * blockDim.x + t;
    int node = g >> 2;
    int lane = g & 3;
    bool valid = node < N;
    int nd = valid ? node : 0;

    const unsigned gmask = 0xFu << ((t & 31) & ~3);

    if (t < 64) { ssum[t] = 0.f; ssq[t] = 0.f; }

    const float4* xr4 = (const float4*)(xr + (size_t)nd * 64) + lane * 4;
    float4 r0 = xr4[0], r1 = xr4[1], r2 = xr4[2], r3 = xr4[3];
    const float4* at4 = (const float4*)att + lane * 4;
    float4 a0 = at4[0], a1 = at4[1], a2 = at4[2], a3 = at4[3];

    int base = valid ? off[nd] : 0;
    int cnt  = valid ? deg[nd] : 0;

    float m = -1e30f, s = 0.f;
    float4 c0 = make_float4(0.f,0.f,0.f,0.f), c1 = c0, c2 = c0, c3 = c0;
    float4 l0, l1, l2, l3;

    if (cnt > 0) {
        int src = __ldg(&srcb[base]);
        const float4* p = (const float4*)(xl + (size_t)src * 64) + lane * 4;
        l0 = p[0]; l1 = p[1]; l2 = p[2]; l3 = p[3];
    }

    for (int j = 0; j < cnt; ++j) {
        float4 n0, n1, n2, n3;
        bool more = (j + 1 < cnt);
        if (more) {
            int ns = __ldg(&srcb[base + j + 1]);
            const float4* p = (const float4*)(xl + (size_t)ns * 64) + lane * 4;
            n0 = p[0]; n1 = p[1]; n2 = p[2]; n3 = p[3];
        }

        float e = 0.f, v;
#define EQ(L, R, A) \
        v = L.x + R.x; e += A.x * fmaxf(v, 0.2f * v); \
        v = L.y + R.y; e += A.y * fmaxf(v, 0.2f * v); \
        v = L.z + R.z; e += A.z * fmaxf(v, 0.2f * v); \
        v = L.w + R.w; e += A.w * fmaxf(v, 0.2f * v);
        EQ(l0, r0, a0) EQ(l1, r1, a1) EQ(l2, r2, a2) EQ(l3, r3, a3)
#undef EQ
        e += __shfl_xor_sync(gmask, e, 1);
        e += __shfl_xor_sync(gmask, e, 2);

        float mn = fmaxf(m, e);
        float sc = __expf(m - mn);
        float p  = __expf(e - mn);
        m = mn;
        s = s * sc + p;
#define AQ(C, L) \
        C.x = C.x * sc + p * L.x; C.y = C.y * sc + p * L.y; \
        C.z = C.z * sc + p * L.z; C.w = C.w * sc + p * L.w;
        AQ(c0, l0) AQ(c1, l1) AQ(c2, l2) AQ(c3, l3)
#undef AQ
        if (more) { l0 = n0; l1 = n1; l2 = n2; l3 = n3; }
    }

    float inv = 1.f / (s + 1e-16f);
    const float4* bq = (const float4*)bias + lane * 4;
    float4 b0 = bq[0], b1 = bq[1], b2 = bq[2], b3 = bq[3];
    float x[16];
#define XQ(q, C, B) \
    x[4*q+0] = C.x * inv + B.x; x[4*q+1] = C.y * inv + B.y; \
    x[4*q+2] = C.z * inv + B.z; x[4*q+3] = C.w * inv + B.w;
    XQ(0, c0, b0) XQ(1, c1, b1) XQ(2, c2, b2) XQ(3, c3, b3)
#undef XQ

    if (valid) {
        float4* o = (float4*)(agg + (size_t)node * 64) + lane * 4;
        o[0] = make_float4(x[0],  x[1],  x[2],  x[3]);
        o[1] = make_float4(x[4],  x[5],  x[6],  x[7]);
        o[2] = make_float4(x[8],  x[9],  x[10], x[11]);
        o[3] = make_float4(x[12], x[13], x[14], x[15]);
    }
    if (!valid) {
#pragma unroll
        for (int i = 0; i < 16; ++i) x[i] = 0.f;
    }

    __syncthreads();   // ssum/ssq zero-init visible
#pragma unroll
    for (int i = 0; i < 16; ++i) {
        float sv = x[i];
        float qv = x[i] * x[i];
        sv += __shfl_down_sync(0xffffffffu, sv, 16);
        sv += __shfl_down_sync(0xffffffffu, sv, 8);
        sv += __shfl_down_sync(0xffffffffu, sv, 4);
        qv += __shfl_down_sync(0xffffffffu, qv, 16);
        qv += __shfl_down_sync(0xffffffffu, qv, 8);
        qv += __shfl_down_sync(0xffffffffu, qv, 4);
        if ((t & 31) < 4) {
            int ch = lane * 16 + i;
            atomicAdd(&ssum[ch], sv);
            atomicAdd(&ssq[ch], qv);
        }
    }
    __syncthreads();
    if (t < 64) {
        atomicAdd(&st[t], ssum[t]);
        atomicAdd(&st[64 + t], ssq[t]);
    }
}

// ---------------- BN prep: st -> (scale, shift); zero st for next layer -----
__global__ void prep_bn(const float* __restrict__ st,
                        const float* __restrict__ gamma,
                        const float* __restrict__ beta,
                        float* __restrict__ bnp,
                        float* __restrict__ st_mut, int N) {
    int t = threadIdx.x;   // 128 threads, 1 block
    float scale = 0.f, shift = 0.f;
    if (t < 64) {
        float invN = 1.f / (float)N;
        float mu  = st[t] * invN;
        float var = st[64 + t] * invN - mu * mu;
        float rs  = rsqrtf(var + 1e-5f);
        scale = gamma[t] * rs;
        shift = beta[t] - mu * scale;
    }
    __syncthreads();       // reads done before zeroing
    if (t < 64) { bnp[t] = scale; bnp[64 + t] = shift; }
    st_mut[t] = 0.f;
}

// ---------------- final head: BN(no affine) on [:,:32], softplus [:,32:] ----
__global__ void final_k(const float* __restrict__ v,
                        const float* __restrict__ st,
                        float* __restrict__ out, int N) {
    int i = blockIdx.x * blockDim.x + threadIdx.x;
    if (i >= N * 64) return;
    int n = i >> 6, c = i & 63;
    float x = v[i];
    if (c < 32) {
        float invN = 1.f / (float)N;
        float mu = st[c] * invN;
        float var = st[64 + c] * invN - mu * mu;
        out[(size_t)n * 32 + c] = (x - mu) * rsqrtf(var + 1e-5f);
    } else {
        float sp = fmaxf(x, 0.f) + log1pf(expf(-fabsf(x)));
        out[(size_t)N * 32 + (size_t)n * 32 + (c - 32)] = sp;
    }
}

// ---------------- host launcher ---------------------------------------------
extern "C" void kernel_launch(void* const* d_in, const int* in_sizes, int n_in,
                              void* d_out, int out_size) {
    const float* x    = (const float*)d_in[0];
    const void*  ei   = d_in[1];
    const float* Wl1  = (const float*)d_in[2];
    const float* Wr1  = (const float*)d_in[3];
    const float* att1 = (const float*)d_in[4];
    const float* b1   = (const float*)d_in[5];
    const float* ga1  = (const float*)d_in[6];
    const float* be1  = (const float*)d_in[7];
    const float* Wl2  = (const float*)d_in[8];
    const float* Wr2  = (const float*)d_in[9];
    const float* att2 = (const float*)d_in[10];
    const float* b2   = (const float*)d_in[11];
    float* out = (float*)d_out;

    const int N  = in_sizes[0] / 128;   // 50000
    const int E  = in_sizes[1] / 2;     // 800000
    const int EE = E + N;               // + self loops

    float *p_xl, *p_xr, *p_agg, *p_st, *p_bnp;
    int *p_srcb, *p_off, *p_deg, *p_cur, *p_bsum, *p_bofs;
    cudaGetSymbolAddress((void**)&p_xl,   g_xl);
    cudaGetSymbolAddress((void**)&p_xr,   g_xr);
    cudaGetSymbolAddress((void**)&p_agg,  g_agg);
    cudaGetSymbolAddress((void**)&p_st,   g_st);
    cudaGetSymbolAddress((void**)&p_bnp,  g_bnp);
    cudaGetSymbolAddress((void**)&p_srcb, g_srcb);
    cudaGetSymbolAddress((void**)&p_off,  g_off);
    cudaGetSymbolAddress((void**)&p_deg,  g_deg);
    cudaGetSymbolAddress((void**)&p_cur,  g_cur);
    cudaGetSymbolAddress((void**)&p_bsum, g_bsum);
    cudaGetSymbolAddress((void**)&p_bofs, g_bofs);

    const int TB = 256;
    const int gEdge  = (EE + TB - 1) / TB;
    const int gGemm  = (N + 127) / 128;
    const int gFuse  = (N * 4 + TB - 1) / TB;
    const int gElem  = (N * 64 + TB - 1) / TB;
    const int gScan  = (N + 1023) / 1024;     // 49 blocks

    // ---- CSR build (shared by both layers) ----
    detect_k<<<1, 32>>>((const int*)ei, E);
    cudaMemsetAsync(p_deg, 0, (size_t)N * sizeof(int));
    hist_k<<<gEdge, TB>>>(ei, p_deg, E, EE);
    blocksum_k<<<gScan, TB>>>(p_deg, p_bsum, N);
    topscan_k<<<1, 128>>>(p_bsum, p_bofs, p_st, gScan);
    fill_k<<<gScan, TB>>>(p_deg, p_bofs, p_off, p_cur, N);
    scatter_k<<<gEdge, TB>>>(ei, p_cur, p_srcb, E, EE);

    // ---- layer 1 ----
    gemm_tf32<<<gGemm, TB>>>(x, Wl1, Wr1, nullptr, p_xl, p_xr, N, 128);
    gat_fused<<<gFuse, TB>>>(p_srcb, p_off, p_deg, p_xl, p_xr, att1, b1,
                             p_agg, p_st, N);
    prep_bn<<<1, 128>>>(p_st, ga1, be1, p_bnp, p_st, N);

    // ---- layer 2 (BN+ReLU fused into gemm A-staging) ----
    gemm_tf32<<<gGemm, TB>>>(p_agg, Wl2, Wr2, p_bnp, p_xl, p_xr, N, 64);
    gat_fused<<<gFuse, TB>>>(p_srcb, p_off, p_deg, p_xl, p_xr, att2, b2,
                             p_agg, p_st, N);
    final_k<<<gElem, TB>>>(p_agg, p_st, out, N);
}